// round 1
// baseline (speedup 1.0000x reference)
#include <cuda_runtime.h>

// Problem constants
#define B_   4
#define C_   256
#define DQK_ 32
#define N_   4096   // 64*64

typedef unsigned long long ull;

// ---------------- scratch (no allocation allowed -> device globals) ----------
__device__ float g_qproj[(size_t)B_ * N_ * DQK_];   // Q projection  [B][N][32]  (softmax columns)
__device__ float g_kproj[(size_t)B_ * N_ * DQK_];   // K projection  [B][N][32]  (softmax rows)
__device__ float g_vproj[(size_t)B_ * N_ * C_];     // V projection  [B][N][256]

// ---------------- packed fp32x2 helpers (Blackwell FFMA2) --------------------
__device__ __forceinline__ ull pack2(float a, float b) {
    ull r;
    asm("mov.b64 %0, {%1, %2};" : "=l"(r)
        : "r"(__float_as_uint(a)), "r"(__float_as_uint(b)));
    return r;
}
__device__ __forceinline__ void unpack2(ull v, float& a, float& b) {
    unsigned lo, hi;
    asm("mov.b64 {%0, %1}, %2;" : "=r"(lo), "=r"(hi) : "l"(v));
    a = __uint_as_float(lo);
    b = __uint_as_float(hi);
}
__device__ __forceinline__ void fma2(ull& d, ull a, ull b) {
    asm("fma.rn.f32x2 %0, %1, %2, %0;" : "+l"(d) : "l"(a), "l"(b));
}
__device__ __forceinline__ void mul2(ull& d, ull a, ull b) {
    asm("mul.rn.f32x2 %0, %1, %2;" : "=l"(d) : "l"(a), "l"(b));
}

// =============================================================================
// Kernel 1: projections.  grid = (N/128, B, 10), block = 128 threads.
//   z==0 : q = Wq x + bq   -> g_qproj
//   z==1 : k = Wk x + bk   -> g_kproj
//   z>=2 : v chunk (z-2)   -> g_vproj channels [32*(z-2), 32*(z-1))
// Each thread owns one pixel n; weights staged transposed in smem (stride 34
// floats: 8B aligned for f32x2 loads, 2-way max bank conflict on fill).
// =============================================================================
__global__ __launch_bounds__(128) void proj_kernel(
    const float* __restrict__ x,
    const float* __restrict__ Wq, const float* __restrict__ bq,
    const float* __restrict__ Wk, const float* __restrict__ bk,
    const float* __restrict__ Wv, const float* __restrict__ bv)
{
    __shared__ float Ws[256 * 34];
    __shared__ float bs[32];

    const int tid  = threadIdx.x;
    const int b    = blockIdx.y;
    const int pass = blockIdx.z;
    const int n    = blockIdx.x * 128 + tid;

    const float* W;
    const float* bias;
    float* dst;
    int stride, coff;
    if (pass == 0)      { W = Wq;                    bias = bq;              dst = g_qproj; stride = DQK_; coff = 0; }
    else if (pass == 1) { W = Wk;                    bias = bk;              dst = g_kproj; stride = DQK_; coff = 0; }
    else { int c8 = pass - 2; W = Wv + (size_t)c8 * 32 * 256; bias = bv + c8 * 32; dst = g_vproj; stride = C_; coff = c8 * 32; }

    // stage W transposed: Ws[c*34 + j] = W[j*256 + c]
    for (int idx = tid; idx < 32 * 256; idx += 128) {
        int j = idx >> 8;
        int c = idx & 255;
        Ws[c * 34 + j] = W[idx];
    }
    if (tid < 32) bs[tid] = bias[tid];
    __syncthreads();

    ull acc[16];
#pragma unroll
    for (int j2 = 0; j2 < 16; ++j2) acc[j2] = pack2(bs[2 * j2], bs[2 * j2 + 1]);

    const float* xb = x + (size_t)b * C_ * N_ + n;
    const ull* W2 = (const ull*)Ws;   // row stride 17 ull

#pragma unroll 2
    for (int c = 0; c < 256; ++c) {
        float xv = xb[(size_t)c * N_];
        ull xx = pack2(xv, xv);
        const ull* wr = W2 + c * 17;
#pragma unroll
        for (int j2 = 0; j2 < 16; ++j2) fma2(acc[j2], wr[j2], xx);
    }

    ull* dp = (ull*)(dst + ((size_t)b * N_ + n) * stride + coff);
#pragma unroll
    for (int j2 = 0; j2 < 16; ++j2) dp[j2] = acc[j2];
}

// =============================================================================
// Kernel 2: fused flash attention + epilogue (gamma*out + x).
// grid = (N/64, B), 256 threads, 2 CTAs/SM.
// Thread (ty=tid/16, tx=tid%16): rows m = m0 + ty + 16*i (i<4),
// channels c = 2*tx + 32*j (j<8) -> 32 f32x2 accumulators.
// =============================================================================
#define KS_OFF 0                      // 64*32*4  = 8192
#define QS_OFF 8192                   // 64*36*4  = 9216
#define VS_OFF 17408                  // 64*256*4 = 65536
#define PS_OFF 82944                  // 64*64*4  = 16384
#define SMEM_BYTES 99328

__global__ __launch_bounds__(256, 2) void flash_kernel(
    const float* __restrict__ x,
    const float* __restrict__ gamma,
    float* __restrict__ out)
{
    extern __shared__ char sm[];
    float* K_s = (float*)(sm + KS_OFF);   // [64][32]
    float* Q_s = (float*)(sm + QS_OFF);   // [64][36] padded
    float* V_s = (float*)(sm + VS_OFF);   // [64][256]
    float* P_s = (float*)(sm + PS_OFF);   // [64][64]

    const int tid = threadIdx.x;
    const int ty  = tid >> 4;     // 0..15
    const int tx  = tid & 15;     // 0..15
    const int b   = blockIdx.y;
    const int m0  = blockIdx.x * 64;

    // load K tile once (this block's softmax rows)
    {
        const float4* ksrc = (const float4*)(g_kproj + ((size_t)b * N_ + m0) * DQK_);
        float4* kdst = (float4*)K_s;
        kdst[tid]       = ksrc[tid];
        kdst[tid + 256] = ksrc[tid + 256];
    }

    ull acc[4][8] = {};
    float row_max[4], row_sum[4];
#pragma unroll
    for (int i = 0; i < 4; ++i) { row_max[i] = -1e30f; row_sum[i] = 0.0f; }

    const ull* K2 = (const ull*)K_s;   // row stride 16 ull
    const ull* Q2 = (const ull*)Q_s;   // row stride 18 ull
    const ull* V2 = (const ull*)V_s;   // row stride 128 ull

    for (int t = 0; t < N_ / 64; ++t) {
        const int n0 = t * 64;
        __syncthreads();   // previous PV done reading Q_s / V_s

        // load Q tile (64 x 32) into padded smem
        {
            const float4* qsrc = (const float4*)(g_qproj + ((size_t)b * N_ + n0) * DQK_);
#pragma unroll
            for (int r = 0; r < 2; ++r) {
                int idx = tid + 256 * r;
                float4 v = qsrc[idx];
                int row = idx >> 3;
                int k4  = (idx & 7) << 2;
                float* q = Q_s + row * 36 + k4;
                q[0] = v.x; q[1] = v.y; q[2] = v.z; q[3] = v.w;
            }
        }
        // load V tile (64 x 256), contiguous copy
        {
            const float4* vsrc = (const float4*)(g_vproj + ((size_t)b * N_ + n0) * C_);
            float4* vdst = (float4*)V_s;
#pragma unroll
            for (int r = 0; r < 16; ++r) vdst[tid + 256 * r] = vsrc[tid + 256 * r];
        }
        __syncthreads();

        // ---- S = K . Q^T, online softmax stats, stage P, rescale acc ----
#pragma unroll
        for (int ih = 0; ih < 2; ++ih) {
            ull s2[2][4] = {};
#pragma unroll
            for (int k2 = 0; k2 < 16; ++k2) {
                ull kv0 = K2[(ty + 16 * (2 * ih + 0)) * 16 + k2];
                ull kv1 = K2[(ty + 16 * (2 * ih + 1)) * 16 + k2];
                ull qv[4];
#pragma unroll
                for (int jn = 0; jn < 4; ++jn) qv[jn] = Q2[(tx + 16 * jn) * 18 + k2];
#pragma unroll
                for (int jn = 0; jn < 4; ++jn) {
                    fma2(s2[0][jn], kv0, qv[jn]);
                    fma2(s2[1][jn], kv1, qv[jn]);
                }
            }
#pragma unroll
            for (int ii = 0; ii < 2; ++ii) {
                const int i = 2 * ih + ii;
                float sv[4];
                float tmax = -1e30f;
#pragma unroll
                for (int jn = 0; jn < 4; ++jn) {
                    float lo, hi;
                    unpack2(s2[ii][jn], lo, hi);
                    sv[jn] = lo + hi;
                    tmax = fmaxf(tmax, sv[jn]);
                }
#pragma unroll
                for (int off = 8; off > 0; off >>= 1)
                    tmax = fmaxf(tmax, __shfl_xor_sync(0xffffffffu, tmax, off, 16));

                float mnew = fmaxf(row_max[i], tmax);
                float corr = __expf(row_max[i] - mnew);
                row_max[i] = mnew;

                float psum = 0.0f;
#pragma unroll
                for (int jn = 0; jn < 4; ++jn) {
                    float p = __expf(sv[jn] - mnew);
                    psum += p;
                    P_s[(ty + 16 * i) * 64 + tx + 16 * jn] = p;
                }
#pragma unroll
                for (int off = 8; off > 0; off >>= 1)
                    psum += __shfl_xor_sync(0xffffffffu, psum, off, 16);
                row_sum[i] = row_sum[i] * corr + psum;

                ull cc = pack2(corr, corr);
#pragma unroll
                for (int j = 0; j < 8; ++j) mul2(acc[i][j], acc[i][j], cc);
            }
        }
        __syncthreads();   // P_s ready

        // ---- PV: acc[m][c] += P[m][n] * V[n][c]  (packed f32x2) ----
        for (int n = 0; n < 64; ++n) {
            const ull* vrow = V2 + n * 128 + tx;
            ull vv[8];
#pragma unroll
            for (int j = 0; j < 8; ++j) vv[j] = vrow[16 * j];
#pragma unroll
            for (int i = 0; i < 4; ++i) {
                float p = P_s[(ty + 16 * i) * 64 + n];
                ull pp = pack2(p, p);
#pragma unroll
                for (int j = 0; j < 8; ++j) fma2(acc[i][j], vv[j], pp);
            }
        }
    }

    // ---- epilogue: divide by row sums, transpose via smem, gamma*out + x ----
    __syncthreads();
    float* stage = (float*)sm;   // [256][65]
#pragma unroll
    for (int i = 0; i < 4; ++i) {
        float inv = 1.0f / row_sum[i];
        int mm = ty + 16 * i;
#pragma unroll
        for (int j = 0; j < 8; ++j) {
            float lo, hi;
            unpack2(acc[i][j], lo, hi);
            int c0 = 2 * tx + 32 * j;
            stage[c0 * 65 + mm]       = lo * inv;
            stage[(c0 + 1) * 65 + mm] = hi * inv;
        }
    }
    __syncthreads();

    const float g = *gamma;
    for (int idx = tid; idx < 256 * 64; idx += 256) {
        int mm = idx & 63;
        int c  = idx >> 6;
        size_t ga = ((size_t)(b * C_ + c)) * N_ + m0 + mm;
        out[ga] = g * stage[c * 65 + mm] + x[ga];
    }
}

// =============================================================================
// launcher
// =============================================================================
extern "C" void kernel_launch(void* const* d_in, const int* in_sizes, int n_in,
                              void* d_out, int out_size)
{
    const float* x     = (const float*)d_in[0];
    const float* Wq    = (const float*)d_in[1];
    const float* bq    = (const float*)d_in[2];
    const float* Wk    = (const float*)d_in[3];
    const float* bk    = (const float*)d_in[4];
    const float* Wv    = (const float*)d_in[5];
    const float* bv    = (const float*)d_in[6];
    const float* gamma = (const float*)d_in[7];
    float* out = (float*)d_out;

    // Attribute is sticky per function; first (non-captured) call sets it, so
    // an ignored error during graph capture is harmless.
    (void)cudaFuncSetAttribute(flash_kernel,
                               cudaFuncAttributeMaxDynamicSharedMemorySize,
                               SMEM_BYTES);

    proj_kernel<<<dim3(N_ / 128, B_, 10), 128>>>(x, Wq, bq, Wk, bk, Wv, bv);
    flash_kernel<<<dim3(N_ / 64, B_), 256, SMEM_BYTES>>>(x, gamma, out);
}

// round 3
// speedup vs baseline: 5.8456x; 5.8456x over previous
#include <cuda_runtime.h>
#include <cuda_bf16.h>
#include <cstdint>

// Problem constants
#define B_   4
#define C_   256
#define DQK_ 32
#define N_   4096   // 64*64

typedef unsigned long long ull;
typedef uint32_t u32;

// ---------------- scratch (no allocation allowed -> device globals) ----------
__device__ __nv_bfloat16 g_q[(size_t)B_ * N_ * DQK_];   // [B][N][32], pre-scaled by log2(e)
__device__ __nv_bfloat16 g_k[(size_t)B_ * N_ * DQK_];   // [B][N][32]
__device__ __nv_bfloat16 g_v[(size_t)B_ * C_ * N_];     // [B][C][N] channel-major

// ---------------- packed fp32x2 helpers --------------------------------------
__device__ __forceinline__ ull pack2(float a, float b) {
    ull r;
    asm("mov.b64 %0, {%1, %2};" : "=l"(r)
        : "r"(__float_as_uint(a)), "r"(__float_as_uint(b)));
    return r;
}
__device__ __forceinline__ void unpack2(ull v, float& a, float& b) {
    unsigned lo, hi;
    asm("mov.b64 {%0, %1}, %2;" : "=r"(lo), "=r"(hi) : "l"(v));
    a = __uint_as_float(lo);
    b = __uint_as_float(hi);
}
__device__ __forceinline__ void fma2(ull& d, ull a, ull b) {
    asm("fma.rn.f32x2 %0, %1, %2, %0;" : "+l"(d) : "l"(a), "l"(b));
}
__device__ __forceinline__ void mul2(ull& d, ull a, ull b) {
    asm("mul.rn.f32x2 %0, %1, %2;" : "=l"(d) : "l"(a), "l"(b));
}
__device__ __forceinline__ u32 pack_bf16x2(float lo, float hi) {
    u32 d;
    asm("cvt.rn.bf16x2.f32 %0, %1, %2;" : "=r"(d) : "f"(hi), "f"(lo));
    return d;
}

// ---------------- mma / ldmatrix / cp.async helpers ---------------------------
__device__ __forceinline__ u32 smem_u32(const void* p) {
    u32 a;
    asm("{ .reg .u64 t; cvta.to.shared.u64 t, %1; cvt.u32.u64 %0, t; }" : "=r"(a) : "l"(p));
    return a;
}
__device__ __forceinline__ void ldm_x4(u32 addr, u32& r0, u32& r1, u32& r2, u32& r3) {
    asm volatile("ldmatrix.sync.aligned.m8n8.x4.shared.b16 {%0,%1,%2,%3}, [%4];"
                 : "=r"(r0), "=r"(r1), "=r"(r2), "=r"(r3) : "r"(addr));
}
__device__ __forceinline__ void mma_bf16(float* d, const u32* a, const u32* b) {
    asm volatile(
        "mma.sync.aligned.m16n8k16.row.col.f32.bf16.bf16.f32 "
        "{%0,%1,%2,%3},{%4,%5,%6,%7},{%8,%9},{%0,%1,%2,%3};"
        : "+f"(d[0]), "+f"(d[1]), "+f"(d[2]), "+f"(d[3])
        : "r"(a[0]), "r"(a[1]), "r"(a[2]), "r"(a[3]), "r"(b[0]), "r"(b[1]));
}
__device__ __forceinline__ void cpa16(u32 dst, const void* src) {
    asm volatile("cp.async.cg.shared.global [%0], [%1], 16;" :: "r"(dst), "l"(src));
}
#define CP_COMMIT  asm volatile("cp.async.commit_group;")
#define CP_WAIT0   asm volatile("cp.async.wait_group 0;")
#define CP_WAIT1   asm volatile("cp.async.wait_group 1;")

__device__ __forceinline__ u32 swz(u32 off) { return off ^ ((off >> 3) & 0x70); }

// =============================================================================
// Kernel 1: projections -> bf16 scratch.
//   pass0: Q = (Wq x + bq) * log2(e)  -> g_q [B][N][32]
//   pass1: K = Wk x + bk              -> g_k [B][N][32]
//   pass>=2: V chunk                  -> g_v [B][C][N]
// =============================================================================
__global__ __launch_bounds__(128) void proj_kernel(
    const float* __restrict__ x,
    const float* __restrict__ Wq, const float* __restrict__ bq,
    const float* __restrict__ Wk, const float* __restrict__ bk,
    const float* __restrict__ Wv, const float* __restrict__ bv)
{
    __shared__ float Ws[256 * 34];
    __shared__ float bs[32];

    const int tid  = threadIdx.x;
    const int b    = blockIdx.y;
    const int pass = blockIdx.z;
    const int n    = blockIdx.x * 128 + tid;

    const float* W;
    const float* bias;
    int coff = 0;
    if (pass == 0)      { W = Wq; bias = bq; }
    else if (pass == 1) { W = Wk; bias = bk; }
    else { int c8 = pass - 2; W = Wv + (size_t)c8 * 32 * 256; bias = bv + c8 * 32; coff = c8 * 32; }

    for (int idx = tid; idx < 32 * 256; idx += 128) {
        int j = idx >> 8;
        int c = idx & 255;
        Ws[c * 34 + j] = W[idx];
    }
    if (tid < 32) bs[tid] = bias[tid];
    __syncthreads();

    ull acc[16];
#pragma unroll
    for (int j2 = 0; j2 < 16; ++j2) acc[j2] = pack2(bs[2 * j2], bs[2 * j2 + 1]);

    const float* xb = x + (size_t)b * C_ * N_ + n;
    const ull* W2 = (const ull*)Ws;

#pragma unroll 2
    for (int c = 0; c < 256; ++c) {
        float xv = xb[(size_t)c * N_];
        ull xx = pack2(xv, xv);
        const ull* wr = W2 + c * 17;
#pragma unroll
        for (int j2 = 0; j2 < 16; ++j2) fma2(acc[j2], wr[j2], xx);
    }

    if (pass <= 1) {
        if (pass == 0) {
            const ull sc = pack2(1.44269504088896f, 1.44269504088896f);
#pragma unroll
            for (int j2 = 0; j2 < 16; ++j2) mul2(acc[j2], acc[j2], sc);
        }
        u32 o[16];
#pragma unroll
        for (int j2 = 0; j2 < 16; ++j2) {
            float lo, hi;
            unpack2(acc[j2], lo, hi);
            o[j2] = pack_bf16x2(lo, hi);
        }
        __nv_bfloat16* base = (pass == 0 ? g_q : g_k) + (size_t)(b * N_ + n) * DQK_;
        uint4* dp = (uint4*)base;
#pragma unroll
        for (int v4 = 0; v4 < 4; ++v4)
            dp[v4] = make_uint4(o[4 * v4], o[4 * v4 + 1], o[4 * v4 + 2], o[4 * v4 + 3]);
    } else {
#pragma unroll
        for (int j2 = 0; j2 < 16; ++j2) {
            float lo, hi;
            unpack2(acc[j2], lo, hi);
            g_v[((size_t)(b * C_ + coff + 2 * j2)) * N_ + n]     = __float2bfloat16(lo);
            g_v[((size_t)(b * C_ + coff + 2 * j2 + 1)) * N_ + n] = __float2bfloat16(hi);
        }
    }
}

// =============================================================================
// Kernel 2: bf16 mma.sync flash attention.
// grid = (64, 4), 256 threads, 2 CTA/SM.
// Per CTA: 64 softmax rows (K positions m0..m0+63). Loop over 32 n-tiles of 64.
//   S phase: warp (wid&3) -> 16 rows, (wid>>2) -> 32 cols.
//   PV phase: warp (wid&1) -> 32 rows, (wid>>1) -> 64 channels.
// SMEM: rowsum[64]f @0 | K 8KB @1024 | Q 2x8KB @9216 | P 8KB @25600 | V 2x32KB @33792
// =============================================================================
#define RS_OFF    0
#define K_OFF     1024
#define Q_OFF     9216
#define P_OFF     25600
#define V_OFF     33792
#define SMEM_F    99328
#define STAGE_OFF 1024

__device__ __forceinline__ void load_qv(u32 sb, char* /*unused*/, int tid, int b, int t) {
    const int buf = t & 1;
    const int n0  = t * 64;
    {
        int row = tid >> 2, ch = tid & 3;
        cpa16(sb + Q_OFF + buf * 8192 + swz(row * 128 + ch * 16),
              g_q + (size_t)(b * N_ + n0 + row) * DQK_ + ch * 8);
    }
    const __nv_bfloat16* vbase = g_v + (size_t)b * C_ * N_ + n0;
#pragma unroll
    for (int r = 0; r < 8; ++r) {
        int idx = tid + 256 * r;
        int c = idx >> 3, ch = idx & 7;
        cpa16(sb + V_OFF + buf * 32768 + swz(c * 128 + ch * 16),
              vbase + (size_t)c * N_ + ch * 8);
    }
}

__global__ __launch_bounds__(256, 2)
void flash_mma(const float* __restrict__ x,
               const float* __restrict__ gamma,
               float* __restrict__ out)
{
    extern __shared__ char sm[];
    const u32 sb = smem_u32(sm);
    const int tid  = threadIdx.x;
    const int wid  = tid >> 5;
    const int lane = tid & 31;
    const int gid  = lane >> 2;   // 0..7
    const int qid  = lane & 3;    // 0..3
    const int b    = blockIdx.y;
    const int m0   = blockIdx.x * 64;

    if (tid < 64) ((float*)sm)[tid] = 0.0f;

    // K tile -> smem (1 cp.async per thread)
    {
        int row = tid >> 2, ch = tid & 3;
        cpa16(sb + K_OFF + swz(row * 128 + ch * 16),
              g_k + (size_t)(b * N_ + m0 + row) * DQK_ + ch * 8);
    }
    CP_COMMIT;
    load_qv(sb, sm, tid, b, 0);
    CP_COMMIT;
    CP_WAIT1;                      // K group done
    __syncthreads();

    // persistent K A-frags: rows (wid&3)*16 .. +15, k = 32 (2 k-steps)
    u32 aK[2][4];
    {
        int row = (wid & 3) * 16 + (lane & 15);
#pragma unroll
        for (int ks = 0; ks < 2; ++ks) {
            u32 addr = sb + K_OFF + swz(row * 128 + (lane >> 4) * 16 + ks * 32);
            ldm_x4(addr, aK[ks][0], aK[ks][1], aK[ks][2], aK[ks][3]);
        }
    }

    float D[2][8][4];
#pragma unroll
    for (int ms = 0; ms < 2; ++ms)
#pragma unroll
        for (int cg = 0; cg < 8; ++cg)
#pragma unroll
            for (int r = 0; r < 4; ++r) D[ms][cg][r] = 0.0f;
    float rs0 = 0.0f, rs1 = 0.0f;

    for (int t = 0; t < N_ / 64; ++t) {
        __syncthreads();           // prev PV done reading buffers
        if (t + 1 < N_ / 64) {
            load_qv(sb, sm, tid, b, t + 1);
            CP_COMMIT;
            CP_WAIT1;              // tile t complete
        } else {
            CP_WAIT0;
        }
        __syncthreads();           // tile t visible to all

        // ---- S = K . Q^T  (per-warp 16x32 tile) ----
        const u32 qb = sb + Q_OFF + (t & 1) * 8192;
        float S[4][4];
#pragma unroll
        for (int ns = 0; ns < 4; ++ns)
#pragma unroll
            for (int r = 0; r < 4; ++r) S[ns][r] = 0.0f;

        u32 bQ[2][2][4];   // [ks][nn-pair][4 regs = 2 n-groups]
#pragma unroll
        for (int nn = 0; nn < 2; ++nn) {
            int nrow = (wid >> 2) * 32 + nn * 16 + (lane & 7) + ((lane >> 4) & 1) * 8;
#pragma unroll
            for (int ks = 0; ks < 2; ++ks) {
                u32 addr = qb + swz(nrow * 128 + ((lane >> 3) & 1) * 16 + ks * 32);
                ldm_x4(addr, bQ[ks][nn][0], bQ[ks][nn][1], bQ[ks][nn][2], bQ[ks][nn][3]);
            }
        }
#pragma unroll
        for (int ns = 0; ns < 4; ++ns)
#pragma unroll
            for (int ks = 0; ks < 2; ++ks)
                mma_bf16(S[ns], aK[ks], &bQ[ks][ns >> 1][(ns & 1) * 2]);

        // ---- P = exp2(S) -> smem bf16; accumulate row sums ----
        {
            const int mlo = (wid & 3) * 16 + gid;
#pragma unroll
            for (int ns = 0; ns < 4; ++ns) {
                float e0, e1, e2, e3;
                asm("ex2.approx.f32 %0, %1;" : "=f"(e0) : "f"(S[ns][0]));
                asm("ex2.approx.f32 %0, %1;" : "=f"(e1) : "f"(S[ns][1]));
                asm("ex2.approx.f32 %0, %1;" : "=f"(e2) : "f"(S[ns][2]));
                asm("ex2.approx.f32 %0, %1;" : "=f"(e3) : "f"(S[ns][3]));
                rs0 += e0 + e1;
                rs1 += e2 + e3;
                int n = (wid >> 2) * 32 + ns * 8 + 2 * qid;
                *(u32*)(sm + P_OFF + swz(mlo * 128 + n * 2))       = pack_bf16x2(e0, e1);
                *(u32*)(sm + P_OFF + swz((mlo + 8) * 128 + n * 2)) = pack_bf16x2(e2, e3);
            }
        }
        __syncthreads();           // P visible

        // ---- PV: D += P . V  (per-warp 32 rows x 64 channels) ----
        const u32 vb = sb + V_OFF + (t & 1) * 32768;
#pragma unroll
        for (int ksn = 0; ksn < 4; ++ksn) {
            u32 aP[2][4];
#pragma unroll
            for (int ms = 0; ms < 2; ++ms) {
                int row = (wid & 1) * 32 + ms * 16 + (lane & 15);
                u32 addr = sb + P_OFF + swz(row * 128 + (lane >> 4) * 16 + ksn * 32);
                ldm_x4(addr, aP[ms][0], aP[ms][1], aP[ms][2], aP[ms][3]);
            }
            u32 bV[4][4];
#pragma unroll
            for (int pp = 0; pp < 4; ++pp) {
                int crow = (wid >> 1) * 64 + pp * 16 + (lane & 7) + ((lane >> 4) & 1) * 8;
                u32 addr = vb + swz(crow * 128 + ((lane >> 3) & 1) * 16 + ksn * 32);
                ldm_x4(addr, bV[pp][0], bV[pp][1], bV[pp][2], bV[pp][3]);
            }
#pragma unroll
            for (int ms = 0; ms < 2; ++ms)
#pragma unroll
                for (int cg = 0; cg < 8; ++cg)
                    mma_bf16(D[ms][cg], aP[ms], &bV[cg >> 1][(cg & 1) * 2]);
        }
    }

    // ---- row sums: 4-lane reduce + cross-warp atomic ----
    __syncthreads();
    rs0 += __shfl_xor_sync(0xffffffffu, rs0, 1);
    rs0 += __shfl_xor_sync(0xffffffffu, rs0, 2);
    rs1 += __shfl_xor_sync(0xffffffffu, rs1, 1);
    rs1 += __shfl_xor_sync(0xffffffffu, rs1, 2);
    if (qid == 0) {
        atomicAdd(&((float*)sm)[(wid & 3) * 16 + gid],     rs0);
        atomicAdd(&((float*)sm)[(wid & 3) * 16 + gid + 8], rs1);
    }
    __syncthreads();

    // ---- stage normalized D as [c][m] for coalesced epilogue ----
    float* stage = (float*)(sm + STAGE_OFF);   // [256][66]
#pragma unroll
    for (int ms = 0; ms < 2; ++ms) {
        int r0 = (wid & 1) * 32 + ms * 16 + gid;
        int r1 = r0 + 8;
        float i0 = 1.0f / ((float*)sm)[r0];
        float i1 = 1.0f / ((float*)sm)[r1];
#pragma unroll
        for (int cg = 0; cg < 8; ++cg) {
            int c = (wid >> 1) * 64 + cg * 8 + 2 * qid;
            stage[c * 66 + r0]       = D[ms][cg][0] * i0;
            stage[(c + 1) * 66 + r0] = D[ms][cg][1] * i0;
            stage[c * 66 + r1]       = D[ms][cg][2] * i1;
            stage[(c + 1) * 66 + r1] = D[ms][cg][3] * i1;
        }
    }
    __syncthreads();

    const float g = gamma[0];
#pragma unroll 4
    for (int i = 0; i < 64; ++i) {
        int m = tid & 63;
        int c = (tid >> 6) + 4 * i;
        size_t ga = ((size_t)(b * C_ + c)) * N_ + m0 + m;
        out[ga] = g * stage[c * 66 + m] + x[ga];
    }
}

// =============================================================================
// launcher
// =============================================================================
extern "C" void kernel_launch(void* const* d_in, const int* in_sizes, int n_in,
                              void* d_out, int out_size)
{
    const float* x     = (const float*)d_in[0];
    const float* Wq    = (const float*)d_in[1];
    const float* bq    = (const float*)d_in[2];
    const float* Wk    = (const float*)d_in[3];
    const float* bk    = (const float*)d_in[4];
    const float* Wv    = (const float*)d_in[5];
    const float* bv    = (const float*)d_in[6];
    const float* gamma = (const float*)d_in[7];
    float* out = (float*)d_out;

    (void)cudaFuncSetAttribute(flash_mma,
                               cudaFuncAttributeMaxDynamicSharedMemorySize,
                               SMEM_F);

    proj_kernel<<<dim3(N_ / 128, B_, 10), 128>>>(x, Wq, bq, Wk, bk, Wv, bv);
    flash_mma<<<dim3(N_ / 64, B_), 256, SMEM_F>>>(x, gamma, out);
}

// round 5
// speedup vs baseline: 8.2864x; 1.4175x over previous
#include <cuda_runtime.h>
#include <cuda_bf16.h>
#include <cstdint>

// Problem constants
#define B_   4
#define C_   256
#define DQK_ 32
#define N_   4096   // 64*64

typedef uint32_t u32;

// ---------------- scratch (no allocation allowed -> device globals) ----------
__device__ __nv_bfloat16 g_q[(size_t)B_ * N_ * DQK_];   // [B][N][32], Q pre-scaled by log2(e)
__device__ __nv_bfloat16 g_k[(size_t)B_ * N_ * DQK_];   // [B][N][32]
__device__ __nv_bfloat16 g_v[(size_t)B_ * C_ * N_];     // [B][C][N] channel-major
__device__ __nv_bfloat16 g_xT[(size_t)B_ * N_ * C_];    // [B][N][C]  x transposed, bf16
__device__ __nv_bfloat16 g_wcat[320 * 256];             // [Wq*log2e; Wk; Wv]
__device__ float         g_bcat[320];                   // [bq*log2e; bk; bv]

// ---------------- helpers ------------------------------------------------------
__device__ __forceinline__ u32 pack_bf16x2(float lo, float hi) {
    u32 d;
    asm("cvt.rn.bf16x2.f32 %0, %1, %2;" : "=r"(d) : "f"(hi), "f"(lo));
    return d;
}
__device__ __forceinline__ u32 smem_u32(const void* p) {
    u32 a;
    asm("{ .reg .u64 t; cvta.to.shared.u64 t, %1; cvt.u32.u64 %0, t; }" : "=r"(a) : "l"(p));
    return a;
}
__device__ __forceinline__ void ldm_x4(u32 addr, u32& r0, u32& r1, u32& r2, u32& r3) {
    asm volatile("ldmatrix.sync.aligned.m8n8.x4.shared.b16 {%0,%1,%2,%3}, [%4];"
                 : "=r"(r0), "=r"(r1), "=r"(r2), "=r"(r3) : "r"(addr));
}
__device__ __forceinline__ void mma_bf16(float* d, const u32* a, const u32* b) {
    asm volatile(
        "mma.sync.aligned.m16n8k16.row.col.f32.bf16.bf16.f32 "
        "{%0,%1,%2,%3},{%4,%5,%6,%7},{%8,%9},{%0,%1,%2,%3};"
        : "+f"(d[0]), "+f"(d[1]), "+f"(d[2]), "+f"(d[3])
        : "r"(a[0]), "r"(a[1]), "r"(a[2]), "r"(a[3]), "r"(b[0]), "r"(b[1]));
}
__device__ __forceinline__ void cpa16(u32 dst, const void* src) {
    asm volatile("cp.async.cg.shared.global [%0], [%1], 16;" :: "r"(dst), "l"(src));
}
#define CP_COMMIT  asm volatile("cp.async.commit_group;")
#define CP_WAIT0   asm volatile("cp.async.wait_group 0;")
#define CP_WAIT1   asm volatile("cp.async.wait_group 1;")

__device__ __forceinline__ u32 swz(u32 off) { return off ^ ((off >> 3) & 0x70); }

#define L2E 1.44269504088896f

// =============================================================================
// Kernel 0a: weight stack + bf16 convert. grid(320), block(256).
// =============================================================================
__global__ void wconv(const float* __restrict__ Wq, const float* __restrict__ bq,
                      const float* __restrict__ Wk, const float* __restrict__ bk,
                      const float* __restrict__ Wv, const float* __restrict__ bv)
{
    int j = blockIdx.x, c = threadIdx.x;
    const float* src;
    float s = 1.0f, bias;
    if (j < 32)       { src = Wq + j * 256;        s = L2E; bias = bq[j] * L2E; }
    else if (j < 64)  { src = Wk + (j - 32) * 256;          bias = bk[j - 32];  }
    else              { src = Wv + (j - 64) * 256;          bias = bv[j - 64];  }
    g_wcat[j * 256 + c] = __float2bfloat16(src[c] * s);
    if (c == 0) g_bcat[j] = bias;
}

// =============================================================================
// Kernel 0b: x [B][C][N] f32 -> g_xT [B][N][C] bf16. grid(64,4,4), block(256).
// =============================================================================
__global__ __launch_bounds__(256) void xT_kernel(const float* __restrict__ x)
{
    __shared__ float T[64][65];
    const int tid = threadIdx.x;
    const int n0 = blockIdx.x * 64, c0 = blockIdx.y * 64, b = blockIdx.z;

    // load 64c x 64n tile (coalesced along n)
    {
        int cr = tid >> 2, q = tid & 3;
        const float4* src = (const float4*)(x + ((size_t)(b * C_ + c0 + cr)) * N_ + n0 + q * 16);
#pragma unroll
        for (int i = 0; i < 4; ++i) {
            float4 v = src[i];
            int nn = q * 16 + i * 4;
            T[cr][nn] = v.x; T[cr][nn + 1] = v.y; T[cr][nn + 2] = v.z; T[cr][nn + 3] = v.w;
        }
    }
    __syncthreads();

    // write [n][c] bf16 rows (coalesced along c)
    u32* dst = (u32*)g_xT;
#pragma unroll
    for (int i = 0; i < 8; ++i) {
        int idx = tid * 8 + i;              // 0..2047
        int n = idx >> 5, cp = idx & 31;
        u32 v = pack_bf16x2(T[2 * cp][n], T[2 * cp + 1][n]);
        dst[((size_t)(b * N_ + n0 + n)) * 128 + (c0 >> 1) + cp] = v;
    }
}

// =============================================================================
// Kernel 1: projection GEMM on tensor cores.
// grid (N/128=32, 5, B=4), 128 threads (4 warps).
//   z==0 : QK mode:  D[pix, j64]  (A = x pixels, B = Wcat rows 0..63)
//   z>=1 : V  mode:  D[ch32x2, pix] (A = Wcat rows z*64.., B = x pixels)
// k = 256 channels in 4 chunks of 64, double-buffered cp.async.
// SMEM: bias 256B @0 | W 2x8KB @1024 | X 2x16KB @17408  => 50176 B
// =============================================================================
#define WT_OFF 1024
#define XT_OFF 17408
#define SMEM_P 50176

__global__ __launch_bounds__(128, 4)
void proj_gemm()
{
    extern __shared__ char sm[];
    const u32 sb = smem_u32(sm);
    float* bs = (float*)sm;
    const int tid = threadIdx.x;
    const int w = tid >> 5, lane = tid & 31;
    const int gid = lane >> 2, qid = lane & 3;
    const int n0 = blockIdx.x * 128;
    const int z  = blockIdx.y;
    const int b  = blockIdx.z;
    const bool qk = (z == 0);
    const int jbase = qk ? 0 : z * 64;

    if (tid < 64) bs[tid] = g_bcat[jbase + tid];

    // chunk loader: W tile [64 j][64 c] = 64x128B, X tile [128 n][64 c] = 128x128B
    auto load_chunk = [&](int kc) {
        int buf = kc & 1;
        // W: 512 cpa16 over 128 threads (4 each)
#pragma unroll
        for (int i = 0; i < 4; ++i) {
            int idx = i * 128 + tid;        // 0..511
            int r = idx >> 3, q = idx & 7;
            cpa16(sb + WT_OFF + buf * 8192 + swz(r * 128 + q * 16),
                  g_wcat + (size_t)(jbase + r) * 256 + kc * 64 + q * 8);
        }
        // X: 1024 cpa16 over 128 threads (8 each)
#pragma unroll
        for (int i = 0; i < 8; ++i) {
            int idx = i * 128 + tid;        // 0..1023
            int r = idx >> 3, q = idx & 7;
            cpa16(sb + XT_OFF + buf * 16384 + swz(r * 128 + q * 16),
                  g_xT + ((size_t)(b * N_) + n0 + r) * 256 + kc * 64 + q * 8);
        }
    };

    load_chunk(0);
    CP_COMMIT;

    float D[2][8][4];
#pragma unroll
    for (int mt = 0; mt < 2; ++mt)
#pragma unroll
        for (int nt = 0; nt < 8; ++nt)
#pragma unroll
            for (int r = 0; r < 4; ++r) D[mt][nt][r] = 0.0f;

    for (int kc = 0; kc < 4; ++kc) {
        if (kc < 3) { load_chunk(kc + 1); CP_COMMIT; CP_WAIT1; }
        else        { CP_WAIT0; }
        __syncthreads();

        const u32 wbase = sb + WT_OFF + (kc & 1) * 8192;
        const u32 xbase = sb + XT_OFF + (kc & 1) * 16384;
        const u32 abase = qk ? xbase : wbase;
        const u32 bbase = qk ? wbase : xbase;
        const int arow  = qk ? w * 32 : (w & 1) * 32;
        const int brow  = qk ? 0 : (w >> 1) * 64;

#pragma unroll
        for (int ks = 0; ks < 4; ++ks) {
            u32 aA[2][4];
#pragma unroll
            for (int mt = 0; mt < 2; ++mt) {
                int row = arow + mt * 16 + (lane & 15);
                ldm_x4(abase + swz(row * 128 + (lane >> 4) * 16 + ks * 32),
                       aA[mt][0], aA[mt][1], aA[mt][2], aA[mt][3]);
            }
#pragma unroll
            for (int ntp = 0; ntp < 4; ++ntp) {
                u32 bB[4];
                int nrow = brow + ntp * 16 + (lane & 7) + ((lane >> 4) & 1) * 8;
                ldm_x4(bbase + swz(nrow * 128 + ((lane >> 3) & 1) * 16 + ks * 32),
                       bB[0], bB[1], bB[2], bB[3]);
                mma_bf16(D[0][2 * ntp],     aA[0], bB);
                mma_bf16(D[0][2 * ntp + 1], aA[0], bB + 2);
                mma_bf16(D[1][2 * ntp],     aA[1], bB);
                mma_bf16(D[1][2 * ntp + 1], aA[1], bB + 2);
            }
        }
        __syncthreads();
    }

    // ---- epilogue: packed coalesced u32 stores ----
    if (qk) {
#pragma unroll
        for (int mt = 0; mt < 2; ++mt) {
            int n = n0 + w * 32 + mt * 16 + gid;
#pragma unroll
            for (int nt = 0; nt < 8; ++nt) {
                int j = nt * 8 + 2 * qid;
                float b0 = bs[j], b1 = bs[j + 1];
                u32 lo = pack_bf16x2(D[mt][nt][0] + b0, D[mt][nt][1] + b1);
                u32 hi = pack_bf16x2(D[mt][nt][2] + b0, D[mt][nt][3] + b1);
                int jj = j < 32 ? j : j - 32;
                u32* dst = (u32*)(j < 32 ? g_q : g_k);
                dst[((size_t)(b * N_) + n) * 16 + (jj >> 1)]       = lo;
                dst[((size_t)(b * N_) + n + 8) * 16 + (jj >> 1)]   = hi;
            }
        }
    } else {
#pragma unroll
        for (int mt = 0; mt < 2; ++mt) {
            int chl = (w & 1) * 32 + mt * 16 + gid;
            int ch  = (z - 1) * 64 + chl;
            float bv0 = bs[chl], bv1 = bs[chl + 8];
#pragma unroll
            for (int nt = 0; nt < 8; ++nt) {
                int pix = (w >> 1) * 64 + nt * 8 + 2 * qid;
                u32 lo = pack_bf16x2(D[mt][nt][0] + bv0, D[mt][nt][1] + bv0);
                u32 hi = pack_bf16x2(D[mt][nt][2] + bv1, D[mt][nt][3] + bv1);
                u32* dst = (u32*)g_v;
                dst[((size_t)(b * C_ + ch)) * 2048 + ((n0 + pix) >> 1)]     = lo;
                dst[((size_t)(b * C_ + ch + 8)) * 2048 + ((n0 + pix) >> 1)] = hi;
            }
        }
    }
}

// =============================================================================
// Kernel 2: bf16 mma.sync flash attention (unchanged from round 3).
// grid = (64, 4), 256 threads, 2 CTA/SM.
// =============================================================================
#define RS_OFF    0
#define K_OFF     1024
#define Q_OFF     9216
#define P_OFF     25600
#define V_OFF     33792
#define SMEM_F    99328
#define STAGE_OFF 1024

__device__ __forceinline__ void load_qv(u32 sb, int tid, int b, int t) {
    const int buf = t & 1;
    const int n0  = t * 64;
    {
        int row = tid >> 2, ch = tid & 3;
        cpa16(sb + Q_OFF + buf * 8192 + swz(row * 128 + ch * 16),
              g_q + (size_t)(b * N_ + n0 + row) * DQK_ + ch * 8);
    }
    const __nv_bfloat16* vbase = g_v + (size_t)b * C_ * N_ + n0;
#pragma unroll
    for (int r = 0; r < 8; ++r) {
        int idx = tid + 256 * r;
        int c = idx >> 3, ch = idx & 7;
        cpa16(sb + V_OFF + buf * 32768 + swz(c * 128 + ch * 16),
              vbase + (size_t)c * N_ + ch * 8);
    }
}

__global__ __launch_bounds__(256, 2)
void flash_mma(const float* __restrict__ x,
               const float* __restrict__ gamma,
               float* __restrict__ out)
{
    extern __shared__ char sm[];
    const u32 sb = smem_u32(sm);
    const int tid  = threadIdx.x;
    const int wid  = tid >> 5;
    const int lane = tid & 31;
    const int gid  = lane >> 2;
    const int qid  = lane & 3;
    const int b    = blockIdx.y;
    const int m0   = blockIdx.x * 64;

    if (tid < 64) ((float*)sm)[tid] = 0.0f;

    {
        int row = tid >> 2, ch = tid & 3;
        cpa16(sb + K_OFF + swz(row * 128 + ch * 16),
              g_k + (size_t)(b * N_ + m0 + row) * DQK_ + ch * 8);
    }
    CP_COMMIT;
    load_qv(sb, tid, b, 0);
    CP_COMMIT;
    CP_WAIT1;
    __syncthreads();

    u32 aK[2][4];
    {
        int row = (wid & 3) * 16 + (lane & 15);
#pragma unroll
        for (int ks = 0; ks < 2; ++ks) {
            u32 addr = sb + K_OFF + swz(row * 128 + (lane >> 4) * 16 + ks * 32);
            ldm_x4(addr, aK[ks][0], aK[ks][1], aK[ks][2], aK[ks][3]);
        }
    }

    float D[2][8][4];
#pragma unroll
    for (int ms = 0; ms < 2; ++ms)
#pragma unroll
        for (int cg = 0; cg < 8; ++cg)
#pragma unroll
            for (int r = 0; r < 4; ++r) D[ms][cg][r] = 0.0f;
    float rs0 = 0.0f, rs1 = 0.0f;

    for (int t = 0; t < N_ / 64; ++t) {
        __syncthreads();
        if (t + 1 < N_ / 64) {
            load_qv(sb, tid, b, t + 1);
            CP_COMMIT;
            CP_WAIT1;
        } else {
            CP_WAIT0;
        }
        __syncthreads();

        const u32 qb = sb + Q_OFF + (t & 1) * 8192;
        float S[4][4];
#pragma unroll
        for (int ns = 0; ns < 4; ++ns)
#pragma unroll
            for (int r = 0; r < 4; ++r) S[ns][r] = 0.0f;

        u32 bQ[2][2][4];
#pragma unroll
        for (int nn = 0; nn < 2; ++nn) {
            int nrow = (wid >> 2) * 32 + nn * 16 + (lane & 7) + ((lane >> 4) & 1) * 8;
#pragma unroll
            for (int ks = 0; ks < 2; ++ks) {
                u32 addr = qb + swz(nrow * 128 + ((lane >> 3) & 1) * 16 + ks * 32);
                ldm_x4(addr, bQ[ks][nn][0], bQ[ks][nn][1], bQ[ks][nn][2], bQ[ks][nn][3]);
            }
        }
#pragma unroll
        for (int ns = 0; ns < 4; ++ns)
#pragma unroll
            for (int ks = 0; ks < 2; ++ks)
                mma_bf16(S[ns], aK[ks], &bQ[ks][ns >> 1][(ns & 1) * 2]);

        {
            const int mlo = (wid & 3) * 16 + gid;
#pragma unroll
            for (int ns = 0; ns < 4; ++ns) {
                float e0, e1, e2, e3;
                asm("ex2.approx.f32 %0, %1;" : "=f"(e0) : "f"(S[ns][0]));
                asm("ex2.approx.f32 %0, %1;" : "=f"(e1) : "f"(S[ns][1]));
                asm("ex2.approx.f32 %0, %1;" : "=f"(e2) : "f"(S[ns][2]));
                asm("ex2.approx.f32 %0, %1;" : "=f"(e3) : "f"(S[ns][3]));
                rs0 += e0 + e1;
                rs1 += e2 + e3;
                int n = (wid >> 2) * 32 + ns * 8 + 2 * qid;
                *(u32*)(sm + P_OFF + swz(mlo * 128 + n * 2))       = pack_bf16x2(e0, e1);
                *(u32*)(sm + P_OFF + swz((mlo + 8) * 128 + n * 2)) = pack_bf16x2(e2, e3);
            }
        }
        __syncthreads();

        const u32 vb = sb + V_OFF + (t & 1) * 32768;
#pragma unroll
        for (int ksn = 0; ksn < 4; ++ksn) {
            u32 aP[2][4];
#pragma unroll
            for (int ms = 0; ms < 2; ++ms) {
                int row = (wid & 1) * 32 + ms * 16 + (lane & 15);
                u32 addr = sb + P_OFF + swz(row * 128 + (lane >> 4) * 16 + ksn * 32);
                ldm_x4(addr, aP[ms][0], aP[ms][1], aP[ms][2], aP[ms][3]);
            }
            u32 bV[4][4];
#pragma unroll
            for (int pp = 0; pp < 4; ++pp) {
                int crow = (wid >> 1) * 64 + pp * 16 + (lane & 7) + ((lane >> 4) & 1) * 8;
                u32 addr = vb + swz(crow * 128 + ((lane >> 3) & 1) * 16 + ksn * 32);
                ldm_x4(addr, bV[pp][0], bV[pp][1], bV[pp][2], bV[pp][3]);
            }
#pragma unroll
            for (int ms = 0; ms < 2; ++ms)
#pragma unroll
                for (int cg = 0; cg < 8; ++cg)
                    mma_bf16(D[ms][cg], aP[ms], &bV[cg >> 1][(cg & 1) * 2]);
        }
    }

    __syncthreads();
    rs0 += __shfl_xor_sync(0xffffffffu, rs0, 1);
    rs0 += __shfl_xor_sync(0xffffffffu, rs0, 2);
    rs1 += __shfl_xor_sync(0xffffffffu, rs1, 1);
    rs1 += __shfl_xor_sync(0xffffffffu, rs1, 2);
    if (qid == 0) {
        atomicAdd(&((float*)sm)[(wid & 3) * 16 + gid],     rs0);
        atomicAdd(&((float*)sm)[(wid & 3) * 16 + gid + 8], rs1);
    }
    __syncthreads();

    float* stage = (float*)(sm + STAGE_OFF);
#pragma unroll
    for (int ms = 0; ms < 2; ++ms) {
        int r0 = (wid & 1) * 32 + ms * 16 + gid;
        int r1 = r0 + 8;
        float i0 = 1.0f / ((float*)sm)[r0];
        float i1 = 1.0f / ((float*)sm)[r1];
#pragma unroll
        for (int cg = 0; cg < 8; ++cg) {
            int c = (wid >> 1) * 64 + cg * 8 + 2 * qid;
            stage[c * 66 + r0]       = D[ms][cg][0] * i0;
            stage[(c + 1) * 66 + r0] = D[ms][cg][1] * i0;
            stage[c * 66 + r1]       = D[ms][cg][2] * i1;
            stage[(c + 1) * 66 + r1] = D[ms][cg][3] * i1;
        }
    }
    __syncthreads();

    const float g = gamma[0];
#pragma unroll 4
    for (int i = 0; i < 64; ++i) {
        int m = tid & 63;
        int c = (tid >> 6) + 4 * i;
        size_t ga = ((size_t)(b * C_ + c)) * N_ + m0 + m;
        out[ga] = g * stage[c * 66 + m] + x[ga];
    }
}

// =============================================================================
// launcher
// =============================================================================
extern "C" void kernel_launch(void* const* d_in, const int* in_sizes, int n_in,
                              void* d_out, int out_size)
{
    const float* x     = (const float*)d_in[0];
    const float* Wq    = (const float*)d_in[1];
    const float* bq    = (const float*)d_in[2];
    const float* Wk    = (const float*)d_in[3];
    const float* bk    = (const float*)d_in[4];
    const float* Wv    = (const float*)d_in[5];
    const float* bv    = (const float*)d_in[6];
    const float* gamma = (const float*)d_in[7];
    float* out = (float*)d_out;

    (void)cudaFuncSetAttribute(proj_gemm,
                               cudaFuncAttributeMaxDynamicSharedMemorySize, SMEM_P);
    (void)cudaFuncSetAttribute(flash_mma,
                               cudaFuncAttributeMaxDynamicSharedMemorySize, SMEM_F);

    wconv<<<320, 256>>>(Wq, bq, Wk, bk, Wv, bv);
    xT_kernel<<<dim3(N_ / 64, C_ / 64, B_), 256>>>(x);
    proj_gemm<<<dim3(N_ / 128, 5, B_), 128, SMEM_P>>>();
    flash_mma<<<dim3(N_ / 64, B_), 256, SMEM_F>>>(x, gamma, out);
}